// round 6
// baseline (speedup 1.0000x reference)
#include <cuda_runtime.h>
#include <cuda_bf16.h>
#include <cstdint>

// Problem shape (fixed by setup_inputs): preds [T,B,C] f32, targets [B,L] i64.
#define TT 128
#define BB 128
#define CC 8192
#define LL 50
#define NSLOT 51   // slot 0 = blank, slots 1..50 = labels

// Dense accumulator: g_acc[b][slot] = sum_t exp(x[t,b,c_slot])/Z[t,b].
// Zero at module load; finish_kernel re-zeroes after reading -> invariant
// holds across graph replays. 26 KB, L2-resident.
__device__ float g_acc[BB * NSLOT];

// Fast exp on the FMA pipe (no MUFU). Add-magic rounding + degree-4 poly
// for 2^f on f in [-0.5, 0.5]. Rel err ~5e-5.
__device__ __forceinline__ float fast_exp(float x) {
    const float L2E = 1.4426950408889634f;
    float t  = fmaf(x, L2E, 12582912.0f);
    float nf = t - 12582912.0f;
    float f  = fmaf(x, L2E, -nf);
    int   ni = __float_as_int(t) - 0x4B400000;
    float sc = __int_as_float((ni << 23) + 0x3F800000);
    float p = fmaf(f, 0.009618129f, 0.05550411f);
    p = fmaf(f, p, 0.2402265f);
    p = fmaf(f, p, 0.6931472f);
    float fp = f * p;
    return fmaf(fp, sc, sc);
}

// ---------------------------------------------------------------------------
// Kernel 1: one block per (t,b) row. Stream 32 KB -> Z; 51 L1-hit gathers;
// 51 fire-and-forget REDG atomicAdds into the dense g_acc[b][*] row.
// No fences, no counters -- the kernel boundary orders everything.
// ---------------------------------------------------------------------------
__global__ __launch_bounds__(256) void zsum_kernel(
    const float* __restrict__ preds,
    const long long* __restrict__ tgt,
    float* __restrict__ out)
{
    int tb  = blockIdx.x;                 // = t*BB + b
    int b   = tb & (BB - 1);
    int tid = threadIdx.x;
    if (tb == 0 && tid == 0) *out = 0.0f;

    // Prefetch label (latency hidden under the 32 KB stream below).
    int c = 0;                            // slot 0 -> blank class 0
    if (tid >= 1 && tid < NSLOT) {
        long long l = tgt[(size_t)b * LL + (tid - 1)];
        if (l > 0 && l < CC) c = (int)l;  // invalid -> class 0 (weight 0 later)
    }

    const float* rowf = preds + (size_t)tb * CC;
    const float4* row = reinterpret_cast<const float4*>(rowf);
    float acc = 0.0f;
#pragma unroll
    for (int i = 0; i < 8; i++) {
        float4 v = row[tid + i * 256];    // 8 front-batched LDG.128
        acc += fast_exp(v.x) + fast_exp(v.y) + fast_exp(v.z) + fast_exp(v.w);
    }
#pragma unroll
    for (int o = 16; o > 0; o >>= 1)
        acc += __shfl_xor_sync(0xFFFFFFFFu, acc, o);

    __shared__ float s[8];
    if ((tid & 31) == 0) s[tid >> 5] = acc;
    __syncthreads();

    if (tid < NSLOT) {
        float z = s[0] + s[1] + s[2] + s[3] + s[4] + s[5] + s[6] + s[7];
        float invz = 1.0f / z;
        // L1-hit gather (row just streamed), then dense REDG accumulate.
        atomicAdd(&g_acc[b * NSLOT + tid], fast_exp(rowf[c]) * invz);
    }
}

// ---------------------------------------------------------------------------
// Kernel 2: PDL-overlapped finisher. Launches while zsum drains; prefetches
// tgt (input, safe pre-sync); griddepcontrol.wait; then reads L2-hot g_acc,
// computes weights/logs, atomicAdds into out, and re-zeroes g_acc.
// ---------------------------------------------------------------------------
__global__ __launch_bounds__(64) void finish_kernel(
    const long long* __restrict__ tgt,
    float* __restrict__ out)
{
    int b   = blockIdx.x;
    int tid = threadIdx.x;

    // Pre-sync phase: prefetch labels (hides cold DRAM latency under zsum).
    float wpos = 0.0f;
    if (tid >= 1 && tid < NSLOT) {
        long long l = tgt[(size_t)b * LL + (tid - 1)];
        wpos = (l > 0 && l < CC) ? 1.0f : 0.0f;
    }

    // npos = sum of wpos over the block (2 warps) -- also pre-sync.
    __shared__ float sw[2];
    float f = wpos;
#pragma unroll
    for (int o = 16; o > 0; o >>= 1)
        f += __shfl_xor_sync(0xFFFFFFFFu, f, o);
    if ((tid & 31) == 0) sw[tid >> 5] = f;
    __syncthreads();
    float npos = sw[0] + sw[1];
    __syncthreads();

    // Wait for zsum completion (all REDG results visible after this).
    asm volatile("griddepcontrol.wait;" ::: "memory");

    const float LOG_T = 4.852030263919617f;    // ln(128)
    float contrib = 0.0f;
    if (tid < NSLOT) {
        float total = g_acc[b * NSLOT + tid];  // L2-hot
        g_acc[b * NSLOT + tid] = 0.0f;         // restore invariant
        float w = (tid == 0) ? ((float)TT - npos) : wpos;
        if (w != 0.0f) contrib = w * (__logf(total) - LOG_T);
    }
#pragma unroll
    for (int o = 16; o > 0; o >>= 1)
        contrib += __shfl_xor_sync(0xFFFFFFFFu, contrib, o);
    if ((tid & 31) == 0) sw[tid >> 5] = contrib;
    __syncthreads();
    if (tid == 0)
        atomicAdd(out, -(sw[0] + sw[1]) * (1.0f / ((float)BB * (float)TT)));
}

extern "C" void kernel_launch(void* const* d_in, const int* in_sizes, int n_in,
                              void* d_out, int out_size)
{
    const float*     preds = (const float*)d_in[0];
    const long long* tgt   = (const long long*)d_in[1];
    float*           out   = (float*)d_out;

    zsum_kernel<<<TT * BB, 256>>>(preds, tgt, out);

    // PDL: let finish_kernel launch while zsum drains; it self-orders via
    // griddepcontrol.wait.
    cudaLaunchConfig_t cfg = {};
    cfg.gridDim  = dim3(BB, 1, 1);
    cfg.blockDim = dim3(64, 1, 1);
    cfg.dynamicSmemBytes = 0;
    cfg.stream = 0;
    cudaLaunchAttribute attr[1];
    attr[0].id = cudaLaunchAttributeProgrammaticStreamSerialization;
    attr[0].val.programmaticStreamSerializationAllowed = 1;
    cfg.attrs = attr;
    cfg.numAttrs = 1;
    cudaLaunchKernelEx(&cfg, finish_kernel, tgt, out);
}